// round 15
// baseline (speedup 1.0000x reference)
#include <cuda_runtime.h>
#include <cuda_fp16.h>
#include <stdint.h>
#include <math.h>

#define E_    2048
#define S_    256
#define Q_    25
#define NN_   36
#define R_    15
#define H_    128
#define K2_   72
#define KP_   80
#define KPW   40            // KP_ in u32 words
#define SR_   3840
#define NPTS  (E_*NN_)      // 73728
#define TPB   2
#define MLP_BLOCKS (NPTS/(128*TPB))      // 288
#define STAGE1_BLOCKS (MLP_BLOCKS + S_)  // 544
#define GX 60               // N tiles (3840/64)
#define GY 32               // M tiles (2048/64)
#define NPART (GX*GY)       // 1920
#define WSU 68              // MLP smem stride (u32)
#define FS  68              // F smem stride (floats)
#define NJ 6

// ---- scratch ----
__device__ __half   g_evH[E_*KP_];
__device__ __half   g_AcatH[SR_*KP_];
__device__ float    g_partial[NPART];
__device__ unsigned g_count = 0;

__device__ __forceinline__ float fast_tanh(float x){
    float y; asm("tanh.approx.f32 %0, %1;" : "=f"(y) : "f"(x)); return y;
}
__device__ __forceinline__ uint32_t pkh(float lo, float hi){
    __half2 h = __floats2half2_rn(lo, hi);
    return *(uint32_t*)&h;
}
__device__ __forceinline__ void cpa16(uint32_t saddr, const void* g){
    asm volatile("cp.async.ca.shared.global [%0], [%1], 16;" :: "r"(saddr), "l"(g));
}
#define CPA_COMMIT() asm volatile("cp.async.commit_group;" ::: "memory")
#define CPA_WAIT0()  asm volatile("cp.async.wait_group 0;" ::: "memory")

__device__ __forceinline__ void hmma16(float* c, const uint32_t* a, const uint32_t* b){
    asm volatile("mma.sync.aligned.m16n8k16.row.col.f32.f16.f16.f32 "
        "{%0,%1,%2,%3},{%4,%5,%6,%7},{%8,%9},{%0,%1,%2,%3};"
        : "+f"(c[0]), "+f"(c[1]), "+f"(c[2]), "+f"(c[3])
        : "r"(a[0]), "r"(a[1]), "r"(a[2]), "r"(a[3]), "r"(b[0]), "r"(b[1]));
}

// ============================================================
// One MLP layer (fp16 mma, proven layout).
// ============================================================
__device__ __forceinline__ void mma_layer(uint32_t* __restrict__ A,
                                          const uint32_t* __restrict__ Wt,
                                          const float* __restrict__ bias,
                                          int l, int mrow, int ncol){
    float c[2][8][4];
    #pragma unroll
    for (int mt = 0; mt < 2; mt++)
        #pragma unroll
        for (int nt = 0; nt < 8; nt++)
            #pragma unroll
            for (int i = 0; i < 4; i++) c[mt][nt][i] = 0.f;

    const int g = l >> 2, t = l & 3;

    #pragma unroll
    for (int kk = 0; kk < 8; kk++){
        const int kw = kk * 8;
        uint32_t a[2][4];
        #pragma unroll
        for (int mt = 0; mt < 2; mt++){
            const int r = mrow + mt*16 + g;
            a[mt][0] = A[ r     *WSU + kw     + t];
            a[mt][1] = A[(r + 8)*WSU + kw     + t];
            a[mt][2] = A[ r     *WSU + kw + 4 + t];
            a[mt][3] = A[(r + 8)*WSU + kw + 4 + t];
        }
        #pragma unroll
        for (int nt = 0; nt < 8; nt++){
            const int n = ncol + nt*8 + g;
            uint32_t b[2];
            b[0] = Wt[n*WSU + kw     + t];
            b[1] = Wt[n*WSU + kw + 4 + t];
            hmma16(c[0][nt], a[0], b);
            hmma16(c[1][nt], a[1], b);
        }
    }
    __syncthreads();

    #pragma unroll
    for (int mt = 0; mt < 2; mt++){
        const int r = mrow + mt*16 + g;
        #pragma unroll
        for (int nt = 0; nt < 8; nt++){
            const int n = ncol + nt*8 + 2*t;
            const float b0 = bias[n], b1 = bias[n+1];
            const int cw = (ncol + nt*8)/2 + t;
            A[ r     *WSU + cw] = pkh(fast_tanh(c[mt][nt][0] + b0),
                                      fast_tanh(c[mt][nt][1] + b1));
            A[(r + 8)*WSU + cw] = pkh(fast_tanh(c[mt][nt][2] + b0),
                                      fast_tanh(c[mt][nt][3] + b1));
        }
    }
    __syncthreads();
}

// ============================================================
// Stage 1: blocks [0,288) MLP (2x128 pts); blocks [288,544) AcatH.
// ============================================================
__global__ __launch_bounds__(256, 2)
void stage1(const float* __restrict__ nodes,
            const float* __restrict__ W1, const float* __restrict__ b1,
            const float* __restrict__ W2, const float* __restrict__ b2,
            const float* __restrict__ W3, const float* __restrict__ b3,
            const float* __restrict__ W4, const float* __restrict__ b4,
            const float* __restrict__ BDD,
            const float* __restrict__ Ixx, const float* __restrict__ Iyy,
            const float* __restrict__ wq,  const float* __restrict__ Base){
    extern __shared__ __align__(16) uint32_t smw[];
    const int tid = threadIdx.x;

    if (blockIdx.x >= MLP_BLOCKS){
        const int s = blockIdx.x - MLP_BLOCKS;
        float* WB  = (float*)smw;
        float* sI0 = WB  + Q_*R_;
        float* sI1 = sI0 + Q_*NN_;
        for (int i = tid; i < Q_*R_; i += 256){
            int q = i / R_, r = i - q*R_;
            WB[i] = wq[q] * Base[q*R_ + r];
        }
        for (int i = tid; i < Q_*NN_; i += 256){
            sI0[i] = Ixx[s*Q_*NN_ + i];
            sI1[i] = Iyy[s*Q_*NN_ + i];
        }
        __syncthreads();
        for (int idx = tid; idx < R_*K2_; idx += 256){
            int r = idx / K2_, n = idx - r*K2_;
            const float* I = (n < NN_) ? sI0 : sI1;
            int nn = (n < NN_) ? n : (n - NN_);
            float acc = 0.f;
            #pragma unroll
            for (int q = 0; q < Q_; q++) acc += WB[q*R_ + r] * I[q*NN_ + nn];
            const int sr = s*R_ + r;
            g_AcatH[sr*KP_ + n] = __float2half(acc);
            if (n < KP_ - K2_) g_AcatH[sr*KP_ + K2_ + n] = __float2half(0.f);
        }
        return;
    }

    // ---------- MLP ----------
    uint32_t* W2t = smw;
    uint32_t* W3t = smw + H_*WSU;
    uint32_t* A   = smw + 2*H_*WSU;
    __shared__ float sW1[2*H_], sB1[H_], sB2[H_], sB3[H_], sW4[H_+1];

    const int w = tid >> 5, l = tid & 31;
    const int mrow = (w & 3) * 32, ncol = (w >> 2) * 64;

    for (int i = tid; i < H_*H_; i += 256){
        int k = i >> 7, n = i & 127;
        ((__half*)W2t)[n*(2*WSU) + k] = __float2half(W2[i]);
        ((__half*)W3t)[n*(2*WSU) + k] = __float2half(W3[i]);
    }
    if (tid < 2*H_) sW1[tid] = W1[tid];
    if (tid < H_){ sB1[tid] = b1[tid]; sB2[tid] = b2[tid]; sB3[tid] = b3[tid]; sW4[tid] = W4[tid]; }
    if (tid == 0) sW4[H_] = b4[0];
    __syncthreads();

    for (int t = 0; t < TPB; t++){
        const int p0 = (blockIdx.x * TPB + t) * 128;

        {
            const int p  = tid >> 1;
            const int jh = (tid & 1) * 64;
            float2 xy = ((const float2*)nodes)[p0 + p];
            #pragma unroll 8
            for (int j = jh; j < jh + 64; j += 2){
                float v0 = fast_tanh(fmaf(xy.x, sW1[j  ], fmaf(xy.y, sW1[H_+j  ], sB1[j  ])));
                float v1 = fast_tanh(fmaf(xy.x, sW1[j+1], fmaf(xy.y, sW1[H_+j+1], sB1[j+1])));
                A[p*WSU + (j >> 1)] = pkh(v0, v1);
            }
        }
        __syncthreads();

        mma_layer(A, W2t, sB2, l, mrow, ncol);
        mma_layer(A, W3t, sB3, l, mrow, ncol);

        if (tid < 128){
            const uint32_t* Af = A + tid*WSU;
            float acc = 0.f;
            #pragma unroll 8
            for (int k = 0; k < H_/2; k++){
                __half2 h = *(const __half2*)&Af[k];
                float2 f = __half22float2(h);
                acc = fmaf(f.x, sW4[2*k], acc);
                acc = fmaf(f.y, sW4[2*k+1], acc);
            }
            float ev = acc + sW4[H_];
            int p = p0 + tid;
            int e = p / NN_, n = p - e*NN_;
            float c00 = __ldg(&BDD[e*4 + 0]), c01 = __ldg(&BDD[e*4 + 1]);
            float c10 = __ldg(&BDD[e*4 + 2]), c11 = __ldg(&BDD[e*4 + 3]);
            g_evH[e*KP_ + n]       = __float2half((c00 + c10) * ev);
            g_evH[e*KP_ + NN_ + n] = __float2half((c01 + c11) * ev);
            if (n < KP_ - K2_) g_evH[e*KP_ + K2_ + n] = __float2half(0.f);
        }
        __syncthreads();
    }
}

// ============================================================
// Stage 2: fp16 mma 64m x 64n tiles; A/B fragments loaded DIRECTLY
// from global (L1/L2 cached) — no smem staging for operands.
// F+J overlapped into smem via cp.async.
// ============================================================
__global__ __launch_bounds__(256, 5)
void gemm_loss(const float* __restrict__ J, const float* __restrict__ F,
               float* __restrict__ out){
    extern __shared__ __align__(16) uint32_t smg[];
    float* Fs = (float*)smg;                 // [64][FS]
    float* Js = Fs + 64*FS;                  // [64][NJ]
    const int tid = threadIdx.x;
    const int m0g = blockIdx.y * 64, n0g = blockIdx.x * 64;
    const int s0  = n0g / R_;

    const uint32_t sbase = (uint32_t)__cvta_generic_to_shared(smg);

    // F tile via cp.async (lands during MMA)
    for (int idx = tid; idx < 64*16; idx += 256){
        int m = idx >> 4, q = idx & 15;
        cpa16(sbase + (m*FS + q*4)*4, F + (m0g + m)*SR_ + n0g + q*4);
    }
    CPA_COMMIT();

    // J slice (regular loads, small)
    for (int idx = tid; idx < 64*NJ; idx += 256){
        int m = idx / NJ, ss = idx - m*NJ;
        int s = s0 + ss;
        Js[64*FS + idx - 64*FS] = 0.f;  // placeholder overwritten below
        Js[idx] = (s < S_) ? -J[(m0g + m)*S_ + s] : 0.f;
    }

    const int w = tid >> 5, l = tid & 31;
    const int g = l >> 2, t = l & 3;
    const int mrow = (w & 3) * 16, ncol = (w >> 2) * 32;

    // direct-global fragment pointers (u32 view; KPW u32 per row)
    const uint32_t* Ag = (const uint32_t*)g_evH   + (size_t)m0g * KPW;
    const uint32_t* Bg = (const uint32_t*)g_AcatH + (size_t)n0g * KPW;
    const int ra = (mrow + g) * KPW;

    float c[4][4];
    #pragma unroll
    for (int nt = 0; nt < 4; nt++)
        #pragma unroll
        for (int i = 0; i < 4; i++) c[nt][i] = 0.f;

    #pragma unroll
    for (int kk = 0; kk < 5; kk++){
        const int kw = kk * 8;
        uint32_t a[4];
        a[0] = __ldg(Ag + ra          + kw     + t);
        a[1] = __ldg(Ag + ra + 8*KPW  + kw     + t);
        a[2] = __ldg(Ag + ra          + kw + 4 + t);
        a[3] = __ldg(Ag + ra + 8*KPW  + kw + 4 + t);
        #pragma unroll
        for (int nt = 0; nt < 4; nt++){
            const int rb = (ncol + nt*8 + g) * KPW;
            uint32_t b[2];
            b[0] = __ldg(Bg + rb + kw     + t);
            b[1] = __ldg(Bg + rb + kw + 4 + t);
            hmma16(c[nt], a, b);
        }
    }

    CPA_WAIT0();
    __syncthreads();

    // fused epilogue from smem
    float lsum = 0.f;
    const int r0 = mrow + g;
    #pragma unroll
    for (int nt = 0; nt < 4; nt++){
        const int nl = ncol + nt*8 + 2*t;
        const int sA = (n0g + nl) / R_ - s0;
        const int sB = (n0g + nl + 1) / R_ - s0;
        float2 f0 = *(const float2*)&Fs[ r0      *FS + nl];
        float2 f1 = *(const float2*)&Fs[(r0 + 8) *FS + nl];
        float ja0 = Js[ r0      *NJ + sA], jb0 = Js[ r0      *NJ + sB];
        float ja1 = Js[(r0 + 8) *NJ + sA], jb1 = Js[(r0 + 8) *NJ + sB];
        float r00 = fmaf(ja0, c[nt][0], -f0.x);
        float r01 = fmaf(jb0, c[nt][1], -f0.y);
        float r10 = fmaf(ja1, c[nt][2], -f1.x);
        float r11 = fmaf(jb1, c[nt][3], -f1.y);
        lsum = fmaf(r00, r00, lsum);
        lsum = fmaf(r01, r01, lsum);
        lsum = fmaf(r10, r10, lsum);
        lsum = fmaf(r11, r11, lsum);
    }

    // warp shfl reduction + one cross-warp round
    #pragma unroll
    for (int o = 16; o > 0; o >>= 1)
        lsum += __shfl_xor_sync(0xFFFFFFFFu, lsum, o);

    __shared__ float red[8];
    __shared__ unsigned s_last;
    if (l == 0) red[w] = lsum;
    __syncthreads();

    if (tid == 0){
        float bsum = red[0] + red[1] + red[2] + red[3]
                   + red[4] + red[5] + red[6] + red[7];
        g_partial[blockIdx.y * GX + blockIdx.x] = bsum;
        __threadfence();
        unsigned t2 = atomicAdd(&g_count, 1u);
        s_last = (t2 == NPART - 1u) ? 1u : 0u;
    }
    __syncthreads();

    if (s_last){
        double s = 0.0;
        for (int i = tid; i < NPART; i += 256) s += (double)g_partial[i];
        __shared__ double dred[256];
        dred[tid] = s; __syncthreads();
        #pragma unroll
        for (int k = 128; k > 0; k >>= 1){
            if (tid < k) dred[tid] += dred[tid + k];
            __syncthreads();
        }
        if (tid == 0){
            out[0] = (float)(dred[0] / (double)R_);
            g_count = 0;
        }
    }
}

// ============================================================
extern "C" void kernel_launch(void* const* d_in, const int* in_sizes, int n_in,
                              void* d_out, int out_size){
    const float* nodes = (const float*)d_in[0];
    const float* W1    = (const float*)d_in[1];
    const float* b1    = (const float*)d_in[2];
    const float* W2    = (const float*)d_in[3];
    const float* b2    = (const float*)d_in[4];
    const float* W3    = (const float*)d_in[5];
    const float* b3    = (const float*)d_in[6];
    const float* W4    = (const float*)d_in[7];
    const float* b4    = (const float*)d_in[8];
    const float* Ixx   = (const float*)d_in[9];
    const float* Iyy   = (const float*)d_in[10];
    const float* BDD   = (const float*)d_in[11];
    const float* wq    = (const float*)d_in[12];
    const float* Base  = (const float*)d_in[13];
    const float* J     = (const float*)d_in[14];
    const float* F     = (const float*)d_in[15];

    const int s1_smem   = 3 * H_ * WSU * 4;              // 104448 B
    const int gemm_smem = (64*FS + 64*NJ) * 4;           // 18944 B
    cudaFuncSetAttribute(stage1,    cudaFuncAttributeMaxDynamicSharedMemorySize, s1_smem);
    cudaFuncSetAttribute(gemm_loss, cudaFuncAttributeMaxDynamicSharedMemorySize, gemm_smem);

    stage1<<<STAGE1_BLOCKS, 256, s1_smem>>>(nodes, W1, b1, W2, b2, W3, b3, W4, b4,
                                            BDD, Ixx, Iyy, wq, Base);
    gemm_loss<<<dim3(GX, GY), 256, gemm_smem>>>(J, F, (float*)d_out);
}

// round 16
// speedup vs baseline: 1.0825x; 1.0825x over previous
#include <cuda_runtime.h>
#include <cuda_fp16.h>
#include <stdint.h>
#include <math.h>

#define E_    2048
#define S_    256
#define Q_    25
#define NN_   36
#define R_    15
#define H_    128
#define K2_   72
#define KP_   80
#define SR_   3840
#define NPTS  (E_*NN_)      // 73728
#define TPB   2
#define MLP_BLOCKS (NPTS/(128*TPB))      // 288
#define STAGE1_BLOCKS (MLP_BLOCKS + S_)  // 544
#define GX 60               // N tiles (3840/64)
#define GY 32               // M tiles (2048/64)
#define NPART (GX*GY)       // 1920
#define WSU 68              // MLP smem stride (u32)
#define GKU 44              // gemm A/B stride (u32)
#define FS  68              // F smem stride (floats)
#define NJ 6

// ---- scratch ----
__device__ __half   g_evH[E_*KP_];
__device__ __half   g_AcatH[SR_*KP_];
__device__ float    g_partial[NPART];
__device__ unsigned g_count = 0;

__device__ __forceinline__ float fast_tanh(float x){
    float y; asm("tanh.approx.f32 %0, %1;" : "=f"(y) : "f"(x)); return y;
}
__device__ __forceinline__ uint32_t pkh(float lo, float hi){
    __half2 h = __floats2half2_rn(lo, hi);
    return *(uint32_t*)&h;
}
__device__ __forceinline__ void cpa16(uint32_t saddr, const void* g){
    asm volatile("cp.async.ca.shared.global [%0], [%1], 16;" :: "r"(saddr), "l"(g));
}
#define CPA_COMMIT() asm volatile("cp.async.commit_group;" ::: "memory")
#define CPA_WAIT1()  asm volatile("cp.async.wait_group 1;" ::: "memory")
#define CPA_WAIT0()  asm volatile("cp.async.wait_group 0;" ::: "memory")

__device__ __forceinline__ void hmma16(float* c, const uint32_t* a, const uint32_t* b){
    asm volatile("mma.sync.aligned.m16n8k16.row.col.f32.f16.f16.f32 "
        "{%0,%1,%2,%3},{%4,%5,%6,%7},{%8,%9},{%0,%1,%2,%3};"
        : "+f"(c[0]), "+f"(c[1]), "+f"(c[2]), "+f"(c[3])
        : "r"(a[0]), "r"(a[1]), "r"(a[2]), "r"(a[3]), "r"(b[0]), "r"(b[1]));
}
__device__ __forceinline__ void ldsm4(uint32_t& r0, uint32_t& r1, uint32_t& r2, uint32_t& r3,
                                      uint32_t addr){
    asm volatile("ldmatrix.sync.aligned.m8n8.x4.shared.b16 {%0,%1,%2,%3}, [%4];"
        : "=r"(r0), "=r"(r1), "=r"(r2), "=r"(r3) : "r"(addr));
}

// ============================================================
// One MLP layer (fp16 mma, proven layout).
// ============================================================
__device__ __forceinline__ void mma_layer(uint32_t* __restrict__ A,
                                          const uint32_t* __restrict__ Wt,
                                          const float* __restrict__ bias,
                                          int l, int mrow, int ncol){
    float c[2][8][4];
    #pragma unroll
    for (int mt = 0; mt < 2; mt++)
        #pragma unroll
        for (int nt = 0; nt < 8; nt++)
            #pragma unroll
            for (int i = 0; i < 4; i++) c[mt][nt][i] = 0.f;

    const int g = l >> 2, t = l & 3;

    #pragma unroll
    for (int kk = 0; kk < 8; kk++){
        const int kw = kk * 8;
        uint32_t a[2][4];
        #pragma unroll
        for (int mt = 0; mt < 2; mt++){
            const int r = mrow + mt*16 + g;
            a[mt][0] = A[ r     *WSU + kw     + t];
            a[mt][1] = A[(r + 8)*WSU + kw     + t];
            a[mt][2] = A[ r     *WSU + kw + 4 + t];
            a[mt][3] = A[(r + 8)*WSU + kw + 4 + t];
        }
        #pragma unroll
        for (int nt = 0; nt < 8; nt++){
            const int n = ncol + nt*8 + g;
            uint32_t b[2];
            b[0] = Wt[n*WSU + kw     + t];
            b[1] = Wt[n*WSU + kw + 4 + t];
            hmma16(c[0][nt], a[0], b);
            hmma16(c[1][nt], a[1], b);
        }
    }
    __syncthreads();

    #pragma unroll
    for (int mt = 0; mt < 2; mt++){
        const int r = mrow + mt*16 + g;
        #pragma unroll
        for (int nt = 0; nt < 8; nt++){
            const int n = ncol + nt*8 + 2*t;
            const float b0 = bias[n], b1 = bias[n+1];
            const int cw = (ncol + nt*8)/2 + t;
            A[ r     *WSU + cw] = pkh(fast_tanh(c[mt][nt][0] + b0),
                                      fast_tanh(c[mt][nt][1] + b1));
            A[(r + 8)*WSU + cw] = pkh(fast_tanh(c[mt][nt][2] + b0),
                                      fast_tanh(c[mt][nt][3] + b1));
        }
    }
    __syncthreads();
}

// ============================================================
// Stage 1: blocks [0,288) MLP (2x128 pts); blocks [288,544) AcatH.
// ============================================================
__global__ __launch_bounds__(256, 2)
void stage1(const float* __restrict__ nodes,
            const float* __restrict__ W1, const float* __restrict__ b1,
            const float* __restrict__ W2, const float* __restrict__ b2,
            const float* __restrict__ W3, const float* __restrict__ b3,
            const float* __restrict__ W4, const float* __restrict__ b4,
            const float* __restrict__ BDD,
            const float* __restrict__ Ixx, const float* __restrict__ Iyy,
            const float* __restrict__ wq,  const float* __restrict__ Base){
    extern __shared__ __align__(16) uint32_t smw[];
    const int tid = threadIdx.x;

    if (blockIdx.x >= MLP_BLOCKS){
        const int s = blockIdx.x - MLP_BLOCKS;
        float* WB  = (float*)smw;
        float* sI0 = WB  + Q_*R_;
        float* sI1 = sI0 + Q_*NN_;
        for (int i = tid; i < Q_*R_; i += 256){
            int q = i / R_, r = i - q*R_;
            WB[i] = wq[q] * Base[q*R_ + r];
        }
        for (int i = tid; i < Q_*NN_; i += 256){
            sI0[i] = Ixx[s*Q_*NN_ + i];
            sI1[i] = Iyy[s*Q_*NN_ + i];
        }
        __syncthreads();
        for (int idx = tid; idx < R_*K2_; idx += 256){
            int r = idx / K2_, n = idx - r*K2_;
            const float* I = (n < NN_) ? sI0 : sI1;
            int nn = (n < NN_) ? n : (n - NN_);
            float acc = 0.f;
            #pragma unroll
            for (int q = 0; q < Q_; q++) acc += WB[q*R_ + r] * I[q*NN_ + nn];
            const int sr = s*R_ + r;
            g_AcatH[sr*KP_ + n] = __float2half(acc);
            if (n < KP_ - K2_) g_AcatH[sr*KP_ + K2_ + n] = __float2half(0.f);
        }
        return;
    }

    // ---------- MLP ----------
    uint32_t* W2t = smw;
    uint32_t* W3t = smw + H_*WSU;
    uint32_t* A   = smw + 2*H_*WSU;
    __shared__ float sW1[2*H_], sB1[H_], sB2[H_], sB3[H_], sW4[H_+1];

    const int w = tid >> 5, l = tid & 31;
    const int mrow = (w & 3) * 32, ncol = (w >> 2) * 64;

    for (int i = tid; i < H_*H_; i += 256){
        int k = i >> 7, n = i & 127;
        ((__half*)W2t)[n*(2*WSU) + k] = __float2half(W2[i]);
        ((__half*)W3t)[n*(2*WSU) + k] = __float2half(W3[i]);
    }
    if (tid < 2*H_) sW1[tid] = W1[tid];
    if (tid < H_){ sB1[tid] = b1[tid]; sB2[tid] = b2[tid]; sB3[tid] = b3[tid]; sW4[tid] = W4[tid]; }
    if (tid == 0) sW4[H_] = b4[0];
    __syncthreads();

    for (int t = 0; t < TPB; t++){
        const int p0 = (blockIdx.x * TPB + t) * 128;

        {
            const int p  = tid >> 1;
            const int jh = (tid & 1) * 64;
            float2 xy = ((const float2*)nodes)[p0 + p];
            #pragma unroll 8
            for (int j = jh; j < jh + 64; j += 2){
                float v0 = fast_tanh(fmaf(xy.x, sW1[j  ], fmaf(xy.y, sW1[H_+j  ], sB1[j  ])));
                float v1 = fast_tanh(fmaf(xy.x, sW1[j+1], fmaf(xy.y, sW1[H_+j+1], sB1[j+1])));
                A[p*WSU + (j >> 1)] = pkh(v0, v1);
            }
        }
        __syncthreads();

        mma_layer(A, W2t, sB2, l, mrow, ncol);
        mma_layer(A, W3t, sB3, l, mrow, ncol);

        if (tid < 128){
            const uint32_t* Af = A + tid*WSU;
            float acc = 0.f;
            #pragma unroll 8
            for (int k = 0; k < H_/2; k++){
                __half2 h = *(const __half2*)&Af[k];
                float2 f = __half22float2(h);
                acc = fmaf(f.x, sW4[2*k], acc);
                acc = fmaf(f.y, sW4[2*k+1], acc);
            }
            float ev = acc + sW4[H_];
            int p = p0 + tid;
            int e = p / NN_, n = p - e*NN_;
            float c00 = __ldg(&BDD[e*4 + 0]), c01 = __ldg(&BDD[e*4 + 1]);
            float c10 = __ldg(&BDD[e*4 + 2]), c11 = __ldg(&BDD[e*4 + 3]);
            g_evH[e*KP_ + n]       = __float2half((c00 + c10) * ev);
            g_evH[e*KP_ + NN_ + n] = __float2half((c01 + c11) * ev);
            if (n < KP_ - K2_) g_evH[e*KP_ + K2_ + n] = __float2half(0.f);
        }
        __syncthreads();
    }
}

// ============================================================
// Stage 2: fp16 mma 64m x 64n tiles, 5 CTAs/SM, ldmatrix frags,
// cp.async F overlap, shfl reduction.
// ============================================================
__global__ __launch_bounds__(256, 5)
void gemm_loss(const float* __restrict__ J, const float* __restrict__ F,
               float* __restrict__ out){
    extern __shared__ __align__(16) uint32_t smg[];
    uint32_t* As = smg;                           // [64][GKU]
    uint32_t* Bs = smg + 64*GKU;                  // [64][GKU]
    float*    Js = (float*)(smg + 128*GKU);       // [64][NJ]
    float*    Fs = Js + 64*NJ;                    // [64][FS]
    __shared__ int sOf[66];
    const int tid = threadIdx.x;
    const int m0g = blockIdx.y * 64, n0g = blockIdx.x * 64;
    const int s0  = n0g / R_;

    const uint32_t sbase = (uint32_t)__cvta_generic_to_shared(smg);

    // group 0: As + Bs
    for (int idx = tid; idx < 64*10; idx += 256){
        int m = idx / 10, q = idx - m*10;
        cpa16(sbase + (m*GKU + q*4)*4, g_evH + (m0g + m)*KP_ + q*8);
    }
    for (int idx = tid; idx < 64*10; idx += 256){
        int n = idx / 10, q = idx - n*10;
        cpa16(sbase + (64*GKU + n*GKU + q*4)*4, g_AcatH + (n0g + n)*KP_ + q*8);
    }
    CPA_COMMIT();

    // group 1: F tile
    const uint32_t fbase = sbase + (128*GKU + 64*NJ)*4;
    for (int idx = tid; idx < 64*16; idx += 256){
        int m = idx >> 4, q = idx & 15;
        cpa16(fbase + (m*FS + q*4)*4, F + (m0g + m)*SR_ + n0g + q*4);
    }
    CPA_COMMIT();

    // J slice + s-offset LUT
    for (int idx = tid; idx < 64*NJ; idx += 256){
        int m = idx / NJ, ss = idx - m*NJ;
        int s = s0 + ss;
        Js[idx] = (s < S_) ? -J[(m0g + m)*S_ + s] : 0.f;
    }
    if (tid < 66) sOf[tid] = (n0g + tid) / R_ - s0;

    CPA_WAIT1();
    __syncthreads();

    const int w = tid >> 5, l = tid & 31;
    const int g = l >> 2, t = l & 3;
    const int mrow = (w & 3) * 16, ncol = (w >> 2) * 32;

    // ldmatrix addresses
    // A x4: lanes 0-15 -> row mrow+lane, col bytes +0; lanes 16-31 -> row mrow+(l&15), +16B
    uint32_t aAddr = sbase + ((mrow + (l & 15))*GKU)*4 + ((l >> 4) << 4);
    // B x4 (2 n-tiles of 8): row = p + ((l>>4)<<3) + (l&7), col bytes ((l>>3)&1)*16
    const int brow = ((l >> 4) << 3) + (l & 7);
    uint32_t bAddr0 = sbase + (64*GKU + (ncol      + brow)*GKU)*4 + (((l >> 3) & 1) << 4);
    uint32_t bAddr1 = sbase + (64*GKU + (ncol + 16 + brow)*GKU)*4 + (((l >> 3) & 1) << 4);

    float c[4][4];
    #pragma unroll
    for (int nt = 0; nt < 4; nt++)
        #pragma unroll
        for (int i = 0; i < 4; i++) c[nt][i] = 0.f;

    #pragma unroll
    for (int kk = 0; kk < 5; kk++){
        uint32_t a[4], b0[4], b1[4];
        ldsm4(a[0], a[1], a[2], a[3], aAddr);
        ldsm4(b0[0], b0[1], b0[2], b0[3], bAddr0);
        ldsm4(b1[0], b1[1], b1[2], b1[3], bAddr1);
        aAddr += 32; bAddr0 += 32; bAddr1 += 32;
        hmma16(c[0], a, b0);
        hmma16(c[1], a, b0 + 2);
        hmma16(c[2], a, b1);
        hmma16(c[3], a, b1 + 2);
    }

    CPA_WAIT0();
    __syncthreads();

    // fused epilogue from smem
    float lsum = 0.f;
    const int r0 = mrow + g;
    #pragma unroll
    for (int nt = 0; nt < 4; nt++){
        const int nl = ncol + nt*8 + 2*t;
        const int sA = sOf[nl], sB = sOf[nl + 1];
        float2 f0 = *(const float2*)&Fs[ r0      *FS + nl];
        float2 f1 = *(const float2*)&Fs[(r0 + 8) *FS + nl];
        float ja0 = Js[ r0      *NJ + sA], jb0 = Js[ r0      *NJ + sB];
        float ja1 = Js[(r0 + 8) *NJ + sA], jb1 = Js[(r0 + 8) *NJ + sB];
        float r00 = fmaf(ja0, c[nt][0], -f0.x);
        float r01 = fmaf(jb0, c[nt][1], -f0.y);
        float r10 = fmaf(ja1, c[nt][2], -f1.x);
        float r11 = fmaf(jb1, c[nt][3], -f1.y);
        lsum = fmaf(r00, r00, lsum);
        lsum = fmaf(r01, r01, lsum);
        lsum = fmaf(r10, r10, lsum);
        lsum = fmaf(r11, r11, lsum);
    }

    // warp shfl reduction + one cross-warp round
    #pragma unroll
    for (int o = 16; o > 0; o >>= 1)
        lsum += __shfl_xor_sync(0xFFFFFFFFu, lsum, o);

    __shared__ float red[8];
    __shared__ unsigned s_last;
    if (l == 0) red[w] = lsum;
    __syncthreads();

    if (tid == 0){
        float bsum = red[0] + red[1] + red[2] + red[3]
                   + red[4] + red[5] + red[6] + red[7];
        g_partial[blockIdx.y * GX + blockIdx.x] = bsum;
        __threadfence();
        unsigned t2 = atomicAdd(&g_count, 1u);
        s_last = (t2 == NPART - 1u) ? 1u : 0u;
    }
    __syncthreads();

    if (s_last){
        double s = 0.0;
        for (int i = tid; i < NPART; i += 256) s += (double)g_partial[i];
        __shared__ double dred[256];
        dred[tid] = s; __syncthreads();
        #pragma unroll
        for (int k = 128; k > 0; k >>= 1){
            if (tid < k) dred[tid] += dred[tid + k];
            __syncthreads();
        }
        if (tid == 0){
            out[0] = (float)(dred[0] / (double)R_);
            g_count = 0;
        }
    }
}

// ============================================================
extern "C" void kernel_launch(void* const* d_in, const int* in_sizes, int n_in,
                              void* d_out, int out_size){
    const float* nodes = (const float*)d_in[0];
    const float* W1    = (const float*)d_in[1];
    const float* b1    = (const float*)d_in[2];
    const float* W2    = (const float*)d_in[3];
    const float* b2    = (const float*)d_in[4];
    const float* W3    = (const float*)d_in[5];
    const float* b3    = (const float*)d_in[6];
    const float* W4    = (const float*)d_in[7];
    const float* b4    = (const float*)d_in[8];
    const float* Ixx   = (const float*)d_in[9];
    const float* Iyy   = (const float*)d_in[10];
    const float* BDD   = (const float*)d_in[11];
    const float* wq    = (const float*)d_in[12];
    const float* Base  = (const float*)d_in[13];
    const float* J     = (const float*)d_in[14];
    const float* F     = (const float*)d_in[15];

    const int s1_smem   = 3 * H_ * WSU * 4;                        // 104448 B
    const int gemm_smem = (128*GKU + 64*NJ + 64*FS) * 4;           // 41984 B
    cudaFuncSetAttribute(stage1,    cudaFuncAttributeMaxDynamicSharedMemorySize, s1_smem);
    cudaFuncSetAttribute(gemm_loss, cudaFuncAttributeMaxDynamicSharedMemorySize, gemm_smem);

    stage1<<<STAGE1_BLOCKS, 256, s1_smem>>>(nodes, W1, b1, W2, b2, W3, b3, W4, b4,
                                            BDD, Ixx, Iyy, wq, Base);
    gemm_loss<<<dim3(GX, GY), 256, gemm_smem>>>(J, F, (float*)d_out);
}